// round 6
// baseline (speedup 1.0000x reference)
#include <cuda_runtime.h>

// TopkWeightClusterLoss, algebraically reduced:
//   d2(q) = (x - q*s)^2 is convex in q => the 15-candidate sequence is V-shaped,
//   top-4 live at the outer q's. With y=|x| the top-4 multiset is exactly:
//     m0 = (y+7s)^2            (also the global max -> e0 = 1)
//     m1 = (y+6s)^2
//     m2 = (max(y+5s, 6s-y))^2
//     m3 = (max(y+4s, 7s-y))^2
//   loss_elem = S - D/E with e_i = exp(m_i - m0), E = 1+e1+e2+e3,
//   S = sum m_i, D = m0 + sum m_i*e_i.

#define ROWS 4096
#define COLS 4096
#define THREADS 256
#define L2E 1.4426950408889634f

__device__ float g_partial[ROWS];
__device__ unsigned int g_count = 0;

__device__ __forceinline__ float ex2f(float x) {
    float r; asm("ex2.approx.f32 %0, %1;" : "=f"(r) : "f"(x)); return r;
}
__device__ __forceinline__ float rcpf(float x) {
    float r; asm("rcp.approx.f32 %0, %1;" : "=f"(r) : "f"(x)); return r;
}

__device__ __forceinline__ float elem_loss(float x, float c4, float c5, float c6, float c7) {
    float y  = fabsf(x);
    float a0 = y + c7;
    float a1 = y + c6;
    float a2 = fmaxf(y + c5, c6 - y);
    float a3 = fmaxf(y + c4, c7 - y);
    float m0 = a0 * a0;
    float m1 = a1 * a1;
    float m2 = a2 * a2;
    float m3 = a3 * a3;
    float t  = -L2E * m0;                 // exp args: log2e*(m_i - m0)
    float e1 = ex2f(fmaf(m1, L2E, t));
    float e2 = ex2f(fmaf(m2, L2E, t));
    float e3 = ex2f(fmaf(m3, L2E, t));
    float E  = (1.0f + e1) + (e2 + e3);
    float S  = (m0 + m1) + (m2 + m3);
    float D  = fmaf(m3, e3, fmaf(m2, e2, fmaf(m1, e1, m0)));
    return fmaf(-D, rcpf(E), S);
}

__global__ __launch_bounds__(THREADS) void topk_loss_fused(
    const float* __restrict__ weight, const float* __restrict__ scale,
    float* __restrict__ out)
{
    const int row = blockIdx.x;
    const float s = __ldg(&scale[row]);
    const float c4 = 4.0f * s, c5 = 5.0f * s, c6 = 6.0f * s, c7 = 7.0f * s;

    const float4* wrow = reinterpret_cast<const float4*>(weight + (size_t)row * COLS);

    float acc = 0.0f;
#pragma unroll
    for (int it = 0; it < COLS / 4 / THREADS; ++it) {
        float4 v = wrow[it * THREADS + threadIdx.x];
        acc += elem_loss(v.x, c4, c5, c6, c7);
        acc += elem_loss(v.y, c4, c5, c6, c7);
        acc += elem_loss(v.z, c4, c5, c6, c7);
        acc += elem_loss(v.w, c4, c5, c6, c7);
    }

    // Deterministic block reduction.
    __shared__ float red[THREADS / 32];
    __shared__ bool s_last;
#pragma unroll
    for (int off = 16; off; off >>= 1)
        acc += __shfl_xor_sync(0xffffffffu, acc, off);
    if ((threadIdx.x & 31) == 0) red[threadIdx.x >> 5] = acc;
    __syncthreads();
    if (threadIdx.x == 0) {
        float v = 0.0f;
#pragma unroll
        for (int i = 0; i < THREADS / 32; ++i) v += red[i];
        g_partial[row] = v;
        __threadfence();
        unsigned int done = atomicAdd(&g_count, 1u);
        s_last = (done == (unsigned)(ROWS - 1));
    }
    __syncthreads();

    // Last block to finish performs the final (fixed-order => deterministic) reduce.
    if (s_last) {
        __threadfence();
        float a = 0.0f;
#pragma unroll
        for (int i = 0; i < ROWS / THREADS; ++i)
            a += g_partial[i * THREADS + threadIdx.x];
#pragma unroll
        for (int off = 16; off; off >>= 1)
            a += __shfl_xor_sync(0xffffffffu, a, off);
        if ((threadIdx.x & 31) == 0) red[threadIdx.x >> 5] = a;
        __syncthreads();
        if (threadIdx.x == 0) {
            float v = 0.0f;
#pragma unroll
            for (int i = 0; i < THREADS / 32; ++i) v += red[i];
            out[0] = v * (0.01f / 3.0f);   // COEFF / (TOPK-1)
            g_count = 0;                   // reset for next graph replay
        }
    }
}

extern "C" void kernel_launch(void* const* d_in, const int* in_sizes, int n_in,
                              void* d_out, int out_size)
{
    const float* weight = (const float*)d_in[0];
    const float* scale  = (const float*)d_in[1];
    float* out = (float*)d_out;

    topk_loss_fused<<<ROWS, THREADS>>>(weight, scale, out);
}

// round 9
// speedup vs baseline: 1.0088x; 1.0088x over previous
#include <cuda_runtime.h>

// TopkWeightClusterLoss, algebraically reduced:
//   d2(q) = (x - q*s)^2 is convex in q => the 15-candidate sequence is V-shaped,
//   top-4 live at the outer q's. With y=|x| the top-4 multiset is exactly:
//     m0 = (y+7s)^2            (also the global max -> e0 = 1)
//     m1 = (y+6s)^2
//     m2 = (max(y+5s, 6s-y))^2
//     m3 = (max(y+4s, 7s-y))^2
//   loss_elem = S - D/E with e_i = exp(m_i - m0), E = 1+e1+e2+e3,
//   S = sum m_i, D = m0 + sum m_i*e_i.

#define ROWS 4096
#define COLS 4096
#define THREADS 256
#define L2E 1.4426950408889634f

__device__ float g_partial[ROWS];
__device__ unsigned int g_count = 0;

__device__ __forceinline__ float ex2f(float x) {
    float r; asm("ex2.approx.f32 %0, %1;" : "=f"(r) : "f"(x)); return r;
}
__device__ __forceinline__ float rcpf(float x) {
    float r; asm("rcp.approx.f32 %0, %1;" : "=f"(r) : "f"(x)); return r;
}

__device__ __forceinline__ float elem_loss(float x, float c4, float c5, float c6, float c7) {
    float y  = fabsf(x);
    float a0 = y + c7;
    float a1 = y + c6;
    float a2 = fmaxf(y + c5, c6 - y);
    float a3 = fmaxf(y + c4, c7 - y);
    float m0 = a0 * a0;
    float m1 = a1 * a1;
    float m2 = a2 * a2;
    float m3 = a3 * a3;
    float t  = -L2E * m0;                 // exp args: log2e*(m_i - m0)
    float e1 = ex2f(fmaf(m1, L2E, t));
    float e2 = ex2f(fmaf(m2, L2E, t));
    float e3 = ex2f(fmaf(m3, L2E, t));
    float E  = (1.0f + e1) + (e2 + e3);
    float S  = (m0 + m1) + (m2 + m3);
    float D  = fmaf(m3, e3, fmaf(m2, e2, fmaf(m1, e1, m0)));
    return fmaf(-D, rcpf(E), S);
}

__global__ __launch_bounds__(THREADS) void topk_loss_fused(
    const float* __restrict__ weight, const float* __restrict__ scale,
    float* __restrict__ out)
{
    const int row = blockIdx.x;
    const float s = __ldg(&scale[row]);
    const float c4 = 4.0f * s, c5 = 5.0f * s, c6 = 6.0f * s, c7 = 7.0f * s;

    const float4* wrow = reinterpret_cast<const float4*>(weight + (size_t)row * COLS);

    float acc = 0.0f;
#pragma unroll
    for (int it = 0; it < COLS / 4 / THREADS; ++it) {
        float4 v = wrow[it * THREADS + threadIdx.x];
        acc += elem_loss(v.x, c4, c5, c6, c7);
        acc += elem_loss(v.y, c4, c5, c6, c7);
        acc += elem_loss(v.z, c4, c5, c6, c7);
        acc += elem_loss(v.w, c4, c5, c6, c7);
    }

    // Deterministic block reduction.
    __shared__ float red[THREADS / 32];
    __shared__ bool s_last;
#pragma unroll
    for (int off = 16; off; off >>= 1)
        acc += __shfl_xor_sync(0xffffffffu, acc, off);
    if ((threadIdx.x & 31) == 0) red[threadIdx.x >> 5] = acc;
    __syncthreads();
    if (threadIdx.x == 0) {
        float v = 0.0f;
#pragma unroll
        for (int i = 0; i < THREADS / 32; ++i) v += red[i];
        g_partial[row] = v;
        __threadfence();
        unsigned int done = atomicAdd(&g_count, 1u);
        s_last = (done == (unsigned)(ROWS - 1));
    }
    __syncthreads();

    // Last block to finish performs the final (fixed-order => deterministic) reduce.
    if (s_last) {
        __threadfence();
        float a = 0.0f;
#pragma unroll
        for (int i = 0; i < ROWS / THREADS; ++i)
            a += g_partial[i * THREADS + threadIdx.x];
#pragma unroll
        for (int off = 16; off; off >>= 1)
            a += __shfl_xor_sync(0xffffffffu, a, off);
        if ((threadIdx.x & 31) == 0) red[threadIdx.x >> 5] = a;
        __syncthreads();
        if (threadIdx.x == 0) {
            float v = 0.0f;
#pragma unroll
            for (int i = 0; i < THREADS / 32; ++i) v += red[i];
            out[0] = v * (0.01f / 3.0f);   // COEFF / (TOPK-1)
            g_count = 0;                   // reset for next graph replay
        }
    }
}

extern "C" void kernel_launch(void* const* d_in, const int* in_sizes, int n_in,
                              void* d_out, int out_size)
{
    const float* weight = (const float*)d_in[0];
    const float* scale  = (const float*)d_in[1];
    float* out = (float*)d_out;

    topk_loss_fused<<<ROWS, THREADS>>>(weight, scale, out);
}